// round 16
// baseline (speedup 1.0000x reference)
#include <cuda_runtime.h>
#include <math.h>

// Problem constants (fixed shapes; derived defensively at launch)
#define LMAX 50
#define MMAX 50
#define PI_F  3.14159265358979323846f
#define TWO_PI_F 6.28318530717958647692f
#define NP 2048          // max point count per batch
#define NB 256           // y-buckets for counting sort
#define BH (PI_F / (float)NB)   // bucket height in y

// ---------------- device scratch (no allocations allowed) ----------------
__device__ float2 g_pxy[4 * NP];            // bucket-sorted (y, x=phi)
__device__ float  g_pr[4 * NP];             // matching rho
__device__ int    g_off[4 * (NB + 1)];      // bucket offsets per batch
__device__ float  g_interp[4 * 131072];     // (B, NLAT*NLON)
__device__ float  g_ctabT[MMAX * 1024];     // [m][j] cos(2*pi*m*j/NLON)
__device__ float  g_xfT[4 * MMAX * 512];    // [b][m][k]

__device__ __forceinline__ int ybucket(float y) {
    // y + pi in [0, pi] -> [0, NB]; monotone in y, clamped
    int bk = (int)((y + PI_F) * ((float)NB / PI_F));
    return min(max(bk, 0), NB - 1);
}

// ---------------- cosine table (transposed): ctabT[m][j] = cos(2*pi*m*j/NLON) ----------------
__global__ void ctabT_kernel(int NLON) {
    int i = blockIdx.x * blockDim.x + threadIdx.x;
    if (i >= NLON * MMAX) return;
    int m = i / NLON;
    int j = i % NLON;
    g_ctabT[m * NLON + j] = cospif((float)(2 * m * j) / (float)NLON);
}

// ---------------- stage 1: cart->sph + counting sort into y-buckets ----------------
// Also zeroes the scalar output (saves a launch).
__global__ __launch_bounds__(512) void prep_bucket_kernel(
    const float* __restrict__ pred, int N, float* __restrict__ out) {
    __shared__ float sy[NP], sx[NP], sr[NP];
    __shared__ int cnt[NB + 1];
    __shared__ int off[NB + 1];
    int b = blockIdx.x;
    int tid = threadIdx.x;
    if (b == 0 && tid == 0) out[0] = 0.0f;
    if (tid <= NB) cnt[tid] = 0;
    __syncthreads();
    for (int i = tid; i < N; i += 512) {
        float x = pred[3 * (b * N + i) + 0];
        float y = pred[3 * (b * N + i) + 1];
        float z = pred[3 * (b * N + i) + 2];
        float rho = sqrtf(x * x + y * y + z * z);
        float yy = acosf(z / rho) - PI_F;
        sy[i] = yy;
        sx[i] = atan2f(y, x);
        sr[i] = rho;
        atomicAdd(&cnt[ybucket(yy)], 1);
    }
    __syncthreads();
    if (tid == 0) {
        int acc = 0;
        for (int i2 = 0; i2 < NB; ++i2) { off[i2] = acc; acc += cnt[i2]; }
        off[NB] = acc;
    }
    __syncthreads();
    if (tid <= NB) {
        g_off[b * (NB + 1) + tid] = off[tid];
        cnt[tid] = 0;               // reuse as per-bucket cursor
    }
    __syncthreads();
    for (int i = tid; i < N; i += 512) {
        int bk = ybucket(sy[i]);
        int pos = off[bk] + atomicAdd(&cnt[bk], 1);
        g_pxy[b * NP + pos] = make_float2(sy[i], sx[i]);
        g_pr[b * NP + pos]  = sr[i];
    }
}

// ---------------- stage 2: exact 3-NN, warp-uniform bucket walk ----------------
// Each WARP owns one longitude column (g1 identical across lanes); each lane
// owns one latitude row (g0 per-lane). Walk/candidate sequence is warp-uniform
// -> zero control divergence. Bucket-edge lower bound with 0.999/-1e-6 slack
// dominates bucketization rounding (validated R12/R13). Candidate distance is
// bit-exact to the reference: round(dx^2) + round(dy^2).
#define KNT6 256

#define KNN_INSERT(dv, jv)                                         \
    if ((dv) < bd2) {                                              \
        float rj = rsm[jv];                                        \
        if ((dv) < bd1) {                                          \
            bd2 = bd1; br2 = br1;                                  \
            if ((dv) < bd0) { bd1 = bd0; br1 = br0;                \
                              bd0 = (dv); br0 = rj; }              \
            else            { bd1 = (dv); br1 = rj; }              \
        } else { bd2 = (dv); br2 = rj; }                           \
    }

__global__ __launch_bounds__(KNT6) void knn6_kernel(
    const float* __restrict__ grid, int M, int NLON, int NROW, int N) {
    __shared__ float2 pxy[NP];
    __shared__ float  rsm[NP];
    __shared__ int off[NB + 1];
    int b    = blockIdx.z;
    int rgrp = blockIdx.y;                 // 32-row group
    int cg   = blockIdx.x;                 // 8-column group
    int w    = threadIdx.x >> 5;
    int lane = threadIdx.x & 31;
    for (int i = threadIdx.x; i < N; i += KNT6) {
        pxy[i] = g_pxy[b * NP + i];
        rsm[i] = g_pr[b * NP + i];
    }
    for (int i = threadIdx.x; i <= NB; i += KNT6) off[i] = g_off[b * (NB + 1) + i];
    __syncthreads();

    int c = cg * 8 + w;                    // column: warp-uniform
    int r = rgrp * 32 + lane;              // row: per-lane
    int m = r * NLON + c;
    float g0 = grid[2 * m];                // row coordinate (per-lane)
    float g1 = grid[2 * m + 1];            // column coordinate (warp-uniform)

    float bd0 = 3.4e38f, bd1 = 3.4e38f, bd2 = 3.4e38f;
    float br0 = 0.0f, br1 = 0.0f, br2 = 0.0f;

    int bc = ybucket(g1);
    int lo = bc, hi = bc + 1;              // next bucket on each side

    while (true) {
        float bl = 1e30f, bh = 1e30f;
        if (lo >= 0) {
            float e = fmaf((float)(lo + 1), BH, -PI_F);   // top edge of bucket lo
            bl = fmaxf((g1 - e) * 0.999f - 1e-6f, 0.0f);
        }
        if (hi < NB) {
            float e = fmaf((float)hi, BH, -PI_F);         // bottom edge of bucket hi
            bh = fmaxf((e - g1) * 0.999f - 1e-6f, 0.0f);
        }
        bool tl = bl <= bh;                // warp-uniform choice
        float bmin = tl ? bl : bh;
        if (__fmul_rn(bmin, bmin) >= bd2) break;  // per-lane exact exit
        int bk;
        if (tl) { bk = lo; --lo; } else { bk = hi; ++hi; }
        int j  = off[bk];
        int o1 = off[bk + 1];
        for (; j + 1 < o1; j += 2) {              // warp-uniform, unrolled x2
            float2 p0 = pxy[j];
            float2 p1 = pxy[j + 1];
            float t0  = g1 - p0.x;
            float dx0 = p0.y - g0;
            float d0  = __fadd_rn(__fmul_rn(dx0, dx0), __fmul_rn(t0, t0));
            float t1  = g1 - p1.x;
            float dx1 = p1.y - g0;
            float d1  = __fadd_rn(__fmul_rn(dx1, dx1), __fmul_rn(t1, t1));
            KNN_INSERT(d0, j);
            KNN_INSERT(d1, j + 1);
        }
        if (j < o1) {
            float2 p0 = pxy[j];
            float t0  = g1 - p0.x;
            float dx0 = p0.y - g0;
            float d0  = __fadd_rn(__fmul_rn(dx0, dx0), __fmul_rn(t0, t0));
            KNN_INSERT(d0, j);
        }
    }

    float s0 = sqrtf(bd0);
    float s1 = sqrtf(bd1);
    float s2 = sqrtf(bd2);
    // weights PROPORTIONAL to distance (as in reference source)
    float v = (s0 * br0 + s1 * br1 + s2 * br2) / (s0 + s1 + s2);
    g_interp[b * M + m] = v;
}

// ---------------- stage 3: warp-per-row, all m interleaved ----------------
// xfT[b][m][k] = (1/NLON) * sum_j interp[bk][j] * ctabT[m][j]
// j-loop outer, 7 per-warp m-accumulators inner: every j-step issues 1 LDS
// broadcast + 7 independent coalesced LDGs + 7 independent FMAs -> no exposed
// dependent-chain latency (fixes xf3's 21.8% issue / 16us profile).
__global__ __launch_bounds__(256) void xf4_kernel(int NLAT, int NLON) {
    __shared__ float srow[512];
    int bk = blockIdx.x;
    int b = bk / NLAT;
    int k = bk % NLAT;
    for (int j = threadIdx.x; j < NLON; j += 256)
        srow[j] = g_interp[bk * NLON + j];
    __syncthreads();
    int w    = threadIdx.x >> 5;
    int lane = threadIdx.x & 31;
    int nm = (w < 2) ? 7 : 6;              // m = w, w+8, ... < 50 (warp-uniform)
    float acc[7];
#pragma unroll
    for (int i = 0; i < 7; ++i) acc[i] = 0.0f;
    const float* ct = g_ctabT + w * NLON + lane;
    for (int j = lane; j < NLON; j += 32) {
        float sv = srow[j];
#pragma unroll 7
        for (int i = 0; i < 7; ++i)
            if (i < nm)
                acc[i] = fmaf(sv, ct[i * 8 * NLON + (j - lane)], acc[i]);
    }
    float inv = 1.0f / (float)NLON;
#pragma unroll 7
    for (int i = 0; i < 7; ++i) {
        if (i < nm) {
            float a = acc[i];
#pragma unroll
            for (int o = 16; o > 0; o >>= 1)
                a += __shfl_down_sync(0xffffffffu, a, o);
            if (lane == 0) {
                int m = w + i * 8;
                g_xfT[(b * MMAX + m) * NLAT + k] = a * inv;
            }
        }
    }
}

// ---------------- stage 4+5 fused: coeff + weighted MSE ----------------
__global__ __launch_bounds__(256) void coeff_loss_kernel(
    const float* __restrict__ pct, const float* __restrict__ target,
    const float* __restrict__ rect, float* __restrict__ out,
    int B, int NLAT) {
    __shared__ float sm[8];
    if (threadIdx.x < 8) sm[threadIdx.x] = 0.0f;
    __syncthreads();
    int w    = blockIdx.x * 8 + (threadIdx.x >> 5);
    int lane = threadIdx.x & 31;
    if (w < B * LMAX * MMAX) {
        int b = w / (LMAX * MMAX);
        int r = w % (LMAX * MMAX);
        int l = r / MMAX;
        int m = r % MMAX;
        const float* xp = g_xfT + (b * MMAX + m) * NLAT;
        const float* pp = pct + (m * LMAX + l) * NLAT;
        float acc = 0.0f;
        for (int k = lane; k < NLAT; k += 32)
            acc = fmaf(xp[k], pp[k], acc);
#pragma unroll
        for (int o = 16; o > 0; o >>= 1)
            acc += __shfl_down_sync(0xffffffffu, acc, o);
        if (lane == 0) {
            float cf = acc * TWO_PI_F;
            float d = cf - target[w];
            sm[threadIdx.x >> 5] = d * d * rect[l] / (float)B;
        }
    }
    __syncthreads();
    if (threadIdx.x == 0) {
        float s = (sm[0] + sm[1]) + (sm[2] + sm[3])
                + (sm[4] + sm[5]) + (sm[6] + sm[7]);
        atomicAdd(out, s);
    }
}

// ---------------- launch ----------------
extern "C" void kernel_launch(void* const* d_in, const int* in_sizes, int n_in,
                              void* d_out, int out_size) {
    const float* pred   = (const float*)d_in[0];
    const float* target = (const float*)d_in[1];
    const float* grid   = (const float*)d_in[2];
    const float* pct    = (const float*)d_in[3];
    const float* rect   = (const float*)d_in[4];

    int B    = in_sizes[1] / (LMAX * MMAX);      // 2
    int N    = in_sizes[0] / (3 * B);            // 2048
    int M    = in_sizes[2] / 2;                  // 131072
    int NLAT = in_sizes[3] / (LMAX * MMAX);      // 256
    int NLON = M / NLAT;                         // 512

    ctabT_kernel<<<(NLON * MMAX + 255) / 256, 256>>>(NLON);
    prep_bucket_kernel<<<B, 512>>>(pred, N, (float*)d_out);

    dim3 kgrid(NLON / 8, NLAT / 32, B);          // 64 x 8 x 2 = 1024 CTAs
    knn6_kernel<<<kgrid, KNT6>>>(grid, M, NLON, NLAT, N);

    xf4_kernel<<<B * NLAT, 256>>>(NLAT, NLON);

    int nout = B * LMAX * MMAX;
    coeff_loss_kernel<<<(nout + 7) / 8, 256>>>(pct, target, rect,
                                               (float*)d_out, B, NLAT);
}

// round 17
// speedup vs baseline: 1.1633x; 1.1633x over previous
#include <cuda_runtime.h>
#include <math.h>

// Problem constants (fixed shapes; derived defensively at launch)
#define LMAX 50
#define MMAX 50
#define PI_F  3.14159265358979323846f
#define TWO_PI_F 6.28318530717958647692f
#define NP 2048          // max point count per batch
#define NB 256           // y-buckets for counting sort
#define BH (PI_F / (float)NB)   // bucket height in y
#define CNLON 512        // compile-time NLON (validated at launch)
#define CNLAT 256        // compile-time NLAT (validated at launch)

// ---------------- device scratch (no allocations allowed) ----------------
__device__ float2 g_pxy[4 * NP];            // bucket-sorted (y, x=phi)
__device__ float  g_pr[4 * NP];             // matching rho
__device__ int    g_off[4 * (NB + 1)];      // bucket offsets per batch
__device__ float  g_interp[4 * 131072];     // (B, NLAT*NLON)
__device__ float  g_ctabT[MMAX * 1024];     // [m][j] cos(2*pi*m*j/NLON)
__device__ float  g_xfT[4 * MMAX * 512];    // [b][m][k]

__device__ __forceinline__ int ybucket(float y) {
    // y + pi in [0, pi] -> [0, NB]; monotone in y, clamped
    int bk = (int)((y + PI_F) * ((float)NB / PI_F));
    return min(max(bk, 0), NB - 1);
}

// ---------------- cosine table (transposed): ctabT[m][j] = cos(2*pi*m*j/NLON) ----------------
__global__ void ctabT_kernel(int NLON) {
    int i = blockIdx.x * blockDim.x + threadIdx.x;
    if (i >= NLON * MMAX) return;
    int m = i / NLON;
    int j = i % NLON;
    g_ctabT[m * NLON + j] = cospif((float)(2 * m * j) / (float)NLON);
}

// ---------------- stage 1: cart->sph + counting sort into y-buckets ----------------
// Also zeroes the scalar output (saves a launch).
__global__ __launch_bounds__(512) void prep_bucket_kernel(
    const float* __restrict__ pred, int N, float* __restrict__ out) {
    __shared__ float sy[NP], sx[NP], sr[NP];
    __shared__ int cnt[NB + 1];
    __shared__ int off[NB + 1];
    int b = blockIdx.x;
    int tid = threadIdx.x;
    if (b == 0 && tid == 0) out[0] = 0.0f;
    if (tid <= NB) cnt[tid] = 0;
    __syncthreads();
    for (int i = tid; i < N; i += 512) {
        float x = pred[3 * (b * N + i) + 0];
        float y = pred[3 * (b * N + i) + 1];
        float z = pred[3 * (b * N + i) + 2];
        float rho = sqrtf(x * x + y * y + z * z);
        float yy = acosf(z / rho) - PI_F;
        sy[i] = yy;
        sx[i] = atan2f(y, x);
        sr[i] = rho;
        atomicAdd(&cnt[ybucket(yy)], 1);
    }
    __syncthreads();
    if (tid == 0) {
        int acc = 0;
        for (int i2 = 0; i2 < NB; ++i2) { off[i2] = acc; acc += cnt[i2]; }
        off[NB] = acc;
    }
    __syncthreads();
    if (tid <= NB) {
        g_off[b * (NB + 1) + tid] = off[tid];
        cnt[tid] = 0;               // reuse as per-bucket cursor
    }
    __syncthreads();
    for (int i = tid; i < N; i += 512) {
        int bk = ybucket(sy[i]);
        int pos = off[bk] + atomicAdd(&cnt[bk], 1);
        g_pxy[b * NP + pos] = make_float2(sy[i], sx[i]);
        g_pr[b * NP + pos]  = sr[i];
    }
}

// ---------------- stage 2: exact 3-NN, warp-uniform bucket walk ----------------
// Each WARP owns one longitude column (g1 identical across lanes); each lane
// owns one latitude row (g0 per-lane). Walk/candidate sequence is warp-uniform
// -> zero control divergence. Bucket-edge lower bound with 0.999/-1e-6 slack
// dominates bucketization rounding (validated R12/R13). Candidate distance is
// bit-exact to the reference: round(dx^2) + round(dy^2).
#define KNT6 256

#define KNN_INSERT(dv, jv)                                         \
    if ((dv) < bd2) {                                              \
        float rj = rsm[jv];                                        \
        if ((dv) < bd1) {                                          \
            bd2 = bd1; br2 = br1;                                  \
            if ((dv) < bd0) { bd1 = bd0; br1 = br0;                \
                              bd0 = (dv); br0 = rj; }              \
            else            { bd1 = (dv); br1 = rj; }              \
        } else { bd2 = (dv); br2 = rj; }                           \
    }

__global__ __launch_bounds__(KNT6) void knn6_kernel(
    const float* __restrict__ grid, int M, int NLON, int NROW, int N) {
    __shared__ float2 pxy[NP];
    __shared__ float  rsm[NP];
    __shared__ int off[NB + 1];
    int b    = blockIdx.z;
    int rgrp = blockIdx.y;                 // 32-row group
    int cg   = blockIdx.x;                 // 8-column group
    int w    = threadIdx.x >> 5;
    int lane = threadIdx.x & 31;
    for (int i = threadIdx.x; i < N; i += KNT6) {
        pxy[i] = g_pxy[b * NP + i];
        rsm[i] = g_pr[b * NP + i];
    }
    for (int i = threadIdx.x; i <= NB; i += KNT6) off[i] = g_off[b * (NB + 1) + i];
    __syncthreads();

    int c = cg * 8 + w;                    // column: warp-uniform
    int r = rgrp * 32 + lane;              // row: per-lane
    int m = r * NLON + c;
    float g0 = grid[2 * m];                // row coordinate (per-lane)
    float g1 = grid[2 * m + 1];            // column coordinate (warp-uniform)

    float bd0 = 3.4e38f, bd1 = 3.4e38f, bd2 = 3.4e38f;
    float br0 = 0.0f, br1 = 0.0f, br2 = 0.0f;

    int bc = ybucket(g1);
    int lo = bc, hi = bc + 1;              // next bucket on each side

    while (true) {
        float bl = 1e30f, bh = 1e30f;
        if (lo >= 0) {
            float e = fmaf((float)(lo + 1), BH, -PI_F);   // top edge of bucket lo
            bl = fmaxf((g1 - e) * 0.999f - 1e-6f, 0.0f);
        }
        if (hi < NB) {
            float e = fmaf((float)hi, BH, -PI_F);         // bottom edge of bucket hi
            bh = fmaxf((e - g1) * 0.999f - 1e-6f, 0.0f);
        }
        bool tl = bl <= bh;                // warp-uniform choice
        float bmin = tl ? bl : bh;
        if (__fmul_rn(bmin, bmin) >= bd2) break;  // per-lane exact exit
        int bk;
        if (tl) { bk = lo; --lo; } else { bk = hi; ++hi; }
        int j  = off[bk];
        int o1 = off[bk + 1];
        for (; j + 1 < o1; j += 2) {              // warp-uniform, unrolled x2
            float2 p0 = pxy[j];
            float2 p1 = pxy[j + 1];
            float t0  = g1 - p0.x;
            float dx0 = p0.y - g0;
            float d0  = __fadd_rn(__fmul_rn(dx0, dx0), __fmul_rn(t0, t0));
            float t1  = g1 - p1.x;
            float dx1 = p1.y - g0;
            float d1  = __fadd_rn(__fmul_rn(dx1, dx1), __fmul_rn(t1, t1));
            KNN_INSERT(d0, j);
            KNN_INSERT(d1, j + 1);
        }
        if (j < o1) {
            float2 p0 = pxy[j];
            float t0  = g1 - p0.x;
            float dx0 = p0.y - g0;
            float d0  = __fadd_rn(__fmul_rn(dx0, dx0), __fmul_rn(t0, t0));
            KNN_INSERT(d0, j);
        }
    }

    float s0 = sqrtf(bd0);
    float s1 = sqrtf(bd1);
    float s2 = sqrtf(bd2);
    // weights PROPORTIONAL to distance (as in reference source)
    float v = (s0 * br0 + s1 * br1 + s2 * br2) / (s0 + s1 + s2);
    g_interp[b * M + m] = v;
}

// ---------------- stage 3: warp-per-(row,m) with fully-unrolled j ----------------
// xfT[b][m][k] = (1/NLON) * sum_j interp[bk][j] * ctabT[m][j]
// Compile-time trip count (CNLON/32 = 16) -> full unroll -> 16 LDGs issued
// back-to-back (MLP 16), latency overlapped. 4 independent accumulators break
// the FMA RAW chain. This fixes xf3/xf4's exposed-LDG-latency profile
// (issue 18-22%, runtime trip count blocked ptxas load batching).
__global__ __launch_bounds__(256) void xf5_kernel() {
    __shared__ float srow[CNLON];
    int bk = blockIdx.x;
    int b = bk / CNLAT;
    int k = bk % CNLAT;
    for (int j = threadIdx.x; j < CNLON; j += 256)
        srow[j] = g_interp[bk * CNLON + j];
    __syncthreads();
    int w    = threadIdx.x >> 5;
    int lane = threadIdx.x & 31;
    const float inv = 1.0f / (float)CNLON;
    for (int m = w; m < MMAX; m += 8) {
        const float* ct = g_ctabT + m * CNLON + lane;
        const float* sr = srow + lane;
        float a0 = 0.f, a1 = 0.f, a2 = 0.f, a3 = 0.f;
#pragma unroll
        for (int t = 0; t < CNLON / 128; ++t) {      // 4 x 4 = 16 steps, unrolled
            a0 = fmaf(sr[t * 128 +  0], ct[t * 128 +  0], a0);
            a1 = fmaf(sr[t * 128 + 32], ct[t * 128 + 32], a1);
            a2 = fmaf(sr[t * 128 + 64], ct[t * 128 + 64], a2);
            a3 = fmaf(sr[t * 128 + 96], ct[t * 128 + 96], a3);
        }
        float acc = (a0 + a1) + (a2 + a3);
#pragma unroll
        for (int o = 16; o > 0; o >>= 1)
            acc += __shfl_down_sync(0xffffffffu, acc, o);
        if (lane == 0)
            g_xfT[(b * MMAX + m) * CNLAT + k] = acc * inv;
    }
}

// ---------------- stage 4+5 fused: coeff + weighted MSE ----------------
// k-loop fully unrolled (CNLAT/32 = 8 steps) -> 16 LDGs batched per warp.
__global__ __launch_bounds__(256) void coeff_loss_kernel(
    const float* __restrict__ pct, const float* __restrict__ target,
    const float* __restrict__ rect, float* __restrict__ out, int B) {
    __shared__ float sm[8];
    if (threadIdx.x < 8) sm[threadIdx.x] = 0.0f;
    __syncthreads();
    int w    = blockIdx.x * 8 + (threadIdx.x >> 5);
    int lane = threadIdx.x & 31;
    if (w < B * LMAX * MMAX) {
        int b = w / (LMAX * MMAX);
        int r = w % (LMAX * MMAX);
        int l = r / MMAX;
        int m = r % MMAX;
        const float* xp = g_xfT + (b * MMAX + m) * CNLAT + lane;
        const float* pp = pct + (m * LMAX + l) * CNLAT + lane;
        float a0 = 0.f, a1 = 0.f;
#pragma unroll
        for (int t = 0; t < CNLAT / 64; ++t) {       // 4 x 2 = 8 steps, unrolled
            a0 = fmaf(xp[t * 64 +  0], pp[t * 64 +  0], a0);
            a1 = fmaf(xp[t * 64 + 32], pp[t * 64 + 32], a1);
        }
        float acc = a0 + a1;
#pragma unroll
        for (int o = 16; o > 0; o >>= 1)
            acc += __shfl_down_sync(0xffffffffu, acc, o);
        if (lane == 0) {
            float cf = acc * TWO_PI_F;
            float d = cf - target[w];
            sm[threadIdx.x >> 5] = d * d * rect[l] / (float)B;
        }
    }
    __syncthreads();
    if (threadIdx.x == 0) {
        float s = (sm[0] + sm[1]) + (sm[2] + sm[3])
                + (sm[4] + sm[5]) + (sm[6] + sm[7]);
        atomicAdd(out, s);
    }
}

// ---------------- launch ----------------
extern "C" void kernel_launch(void* const* d_in, const int* in_sizes, int n_in,
                              void* d_out, int out_size) {
    const float* pred   = (const float*)d_in[0];
    const float* target = (const float*)d_in[1];
    const float* grid   = (const float*)d_in[2];
    const float* pct    = (const float*)d_in[3];
    const float* rect   = (const float*)d_in[4];

    int B    = in_sizes[1] / (LMAX * MMAX);      // 2
    int N    = in_sizes[0] / (3 * B);            // 2048
    int M    = in_sizes[2] / 2;                  // 131072
    int NLAT = in_sizes[3] / (LMAX * MMAX);      // 256
    int NLON = M / NLAT;                         // 512

    ctabT_kernel<<<(NLON * MMAX + 255) / 256, 256>>>(NLON);
    prep_bucket_kernel<<<B, 512>>>(pred, N, (float*)d_out);

    dim3 kgrid(NLON / 8, NLAT / 32, B);          // 64 x 8 x 2 = 1024 CTAs
    knn6_kernel<<<kgrid, KNT6>>>(grid, M, NLON, NLAT, N);

    xf5_kernel<<<B * NLAT, 256>>>();

    int nout = B * LMAX * MMAX;
    coeff_loss_kernel<<<(nout + 7) / 8, 256>>>(pct, target, rect,
                                               (float*)d_out, B);
}